// round 8
// baseline (speedup 1.0000x reference)
#include <cuda_runtime.h>

// HexaToParallelogram: out[bs, q, r] = hexa[bs, pix(q,r)] for valid hex cells
// (|q+r| <= 18), 0.0 for corner cells. In: [32768, 1039] fp32 (first 1027 used),
// out: [32768, 1369] fp32.
//
// Direct gmem->gmem copy. Since 1369 % 4 == 1, output float4 alignment repeats
// every 4 bs-rows (supertile = 4*1369 = 5476 floats = 1369 float4s). Each thread
// owns one float4 slot v of the supertile, computes its (row-in-supertile, src,
// valid) tuple ONCE, then grid-strides over supertiles with only pointer bumps:
// 4 predicated LDG.32 (contiguous across lanes, L1-cached so the 4 stride-16B
// loads reuse each other's sectors) + 1 STG.128 per iteration.
// Unroll 4 -> 16 loads in flight per thread.

#define W          37
#define CELLS      1369              // 37*37
#define IN_STRIDE  1039
#define TPB        256
#define SLOTS      1369              // float4 slots per supertile
#define GROUPS     512               // concurrent supertile streams

__device__ __forceinline__ int src_index(int j) {
    int qi = j / W;              // constant divisor -> mulhi
    int ri = j - qi * W;
    int s = qi + ri;
    if (s < 18 || s > 54) return -1;   // padding corner
    if (qi <= 18) {
        return 19 * qi + (qi * (qi - 1)) / 2 + (ri + qi - 18);
    } else {
        int q = qi - 18;
        return 495 + 37 * q - (q * (q - 1)) / 2 + ri;
    }
}

__global__ void __launch_bounds__(TPB)
hexa_direct_kernel(const float* __restrict__ hexa,
                   float* __restrict__ out,
                   int n_super) {
    int t = blockIdx.x * TPB + threadIdx.x;
    if (t >= SLOTS * GROUPS) return;
    int v = t % SLOTS;           // float4 slot within supertile (one-time div)
    int s = t / SLOTS;           // starting supertile
    if (s >= n_super) return;

    // One-time setup: resolve the 4 elements of this slot.
    int f  = 4 * v;              // flat float index in supertile [0, 5476)
    int lr = f / CELLS;          // row within supertile (0..3)
    int j0 = f - lr * CELLS;

    int  off[4];                 // input offset within supertile (floats)
    bool val[4];
    #pragma unroll
    for (int e = 0; e < 4; e++) {
        int j = j0 + e;
        int lrr = lr;
        if (j >= CELLS) { j -= CELLS; lrr++; }
        int src = src_index(j);
        val[e] = (src >= 0);
        off[e] = lrr * IN_STRIDE + (src >= 0 ? src : 0);
    }

    const float* __restrict__ ip = hexa + (size_t)s * (4 * IN_STRIDE);
    float4* __restrict__ op = (float4*)(out + (size_t)s * (4 * CELLS)) + v;

    const size_t ip_step = (size_t)GROUPS * (4 * IN_STRIDE);
    const size_t op_step = (size_t)GROUPS * CELLS;   // in float4s

    #pragma unroll 4
    for (; s < n_super; s += GROUPS) {
        float4 o;
        o.x = val[0] ? __ldg(ip + off[0]) : 0.0f;
        o.y = val[1] ? __ldg(ip + off[1]) : 0.0f;
        o.z = val[2] ? __ldg(ip + off[2]) : 0.0f;
        o.w = val[3] ? __ldg(ip + off[3]) : 0.0f;
        *op = o;
        ip += ip_step;
        op += op_step;
    }
}

// Fallback scalar kernel for any tail rows (total_rows % 4 != 0)
__global__ void __launch_bounds__(TPB)
hexa_tail_kernel(const float* __restrict__ hexa,
                 float* __restrict__ out,
                 int row_start, int total_rows) {
    int j = blockIdx.x * TPB + threadIdx.x;
    if (j >= CELLS) return;
    int src = src_index(j);
    for (int row = row_start + blockIdx.y; row < total_rows; row += gridDim.y) {
        float v = (src >= 0) ? __ldg(hexa + (size_t)row * IN_STRIDE + src) : 0.0f;
        out[(size_t)row * CELLS + j] = v;
    }
}

extern "C" void kernel_launch(void* const* d_in, const int* in_sizes, int n_in,
                              void* d_out, int out_size) {
    const float* hexa = (const float*)d_in[0];
    float* out = (float*)d_out;

    int total_rows = out_size / CELLS;       // 32768
    int n_super = total_rows / 4;            // 8192
    if (n_super > 0) {
        int threads = SLOTS * GROUPS;            // 700,928
        int blocks = (threads + TPB - 1) / TPB;  // 2738
        hexa_direct_kernel<<<blocks, TPB>>>(hexa, out, n_super);
    }
    int done = n_super * 4;
    if (done < total_rows) {
        dim3 grid((CELLS + TPB - 1) / TPB, total_rows - done);
        hexa_tail_kernel<<<grid, TPB>>>(hexa, out, done, total_rows);
    }
}

// round 9
// speedup vs baseline: 1.0682x; 1.0682x over previous
#include <cuda_runtime.h>

// HexaToParallelogram: out[bs, q, r] = hexa[bs, pix(q,r)] for valid hex cells
// (|q+r| <= 18), 0.0 for corner cells. In: [32768, 1039] fp32 (first 1027 used),
// out: [32768, 1369] fp32.
//
// Direct gmem->gmem copy. Since 1369 % 4 == 1, output float4 alignment repeats
// every 4 bs-rows (supertile = 4*1369 = 5476 floats = 1369 float4s). Each thread
// owns one float4 slot v of the supertile, computes its (row-in-supertile, src,
// valid) tuple ONCE, then grid-strides over supertiles with only pointer bumps:
// 4 predicated LDG.32 (lane-contiguous regions, L1 sector dedup) + 1 STG.128.
//
// GROUPS=442 -> 2364 blocks = 1.997 waves at 8 blocks/SM x 148 SMs (regs=32
// fills the RF exactly), eliminating the 0.31 partial-wave tail of GROUPS=512.

#define W          37
#define CELLS      1369              // 37*37
#define IN_STRIDE  1039
#define TPB        256
#define SLOTS      1369              // float4 slots per supertile
#define GROUPS     442               // concurrent supertile streams (2.0 waves)

__device__ __forceinline__ int src_index(int j) {
    int qi = j / W;              // constant divisor -> mulhi
    int ri = j - qi * W;
    int s = qi + ri;
    if (s < 18 || s > 54) return -1;   // padding corner
    if (qi <= 18) {
        return 19 * qi + (qi * (qi - 1)) / 2 + (ri + qi - 18);
    } else {
        int q = qi - 18;
        return 495 + 37 * q - (q * (q - 1)) / 2 + ri;
    }
}

__global__ void __launch_bounds__(TPB)
hexa_direct_kernel(const float* __restrict__ hexa,
                   float* __restrict__ out,
                   int n_super) {
    int t = blockIdx.x * TPB + threadIdx.x;
    if (t >= SLOTS * GROUPS) return;
    int v = t % SLOTS;           // float4 slot within supertile (one-time div)
    int s = t / SLOTS;           // starting supertile
    if (s >= n_super) return;

    // One-time setup: resolve the 4 elements of this slot.
    int f  = 4 * v;              // flat float index in supertile [0, 5476)
    int lr = f / CELLS;          // row within supertile (0..3)
    int j0 = f - lr * CELLS;

    int  off[4];                 // input offset within supertile (floats)
    bool val[4];
    #pragma unroll
    for (int e = 0; e < 4; e++) {
        int j = j0 + e;
        int lrr = lr;
        if (j >= CELLS) { j -= CELLS; lrr++; }
        int src = src_index(j);
        val[e] = (src >= 0);
        off[e] = lrr * IN_STRIDE + (src >= 0 ? src : 0);
    }

    const float* __restrict__ ip = hexa + (size_t)s * (4 * IN_STRIDE);
    float4* __restrict__ op = (float4*)(out + (size_t)s * (4 * CELLS)) + v;

    const size_t ip_step = (size_t)GROUPS * (4 * IN_STRIDE);
    const size_t op_step = (size_t)GROUPS * CELLS;   // in float4s

    #pragma unroll 2
    for (; s < n_super; s += GROUPS) {
        float4 o;
        o.x = val[0] ? __ldg(ip + off[0]) : 0.0f;
        o.y = val[1] ? __ldg(ip + off[1]) : 0.0f;
        o.z = val[2] ? __ldg(ip + off[2]) : 0.0f;
        o.w = val[3] ? __ldg(ip + off[3]) : 0.0f;
        *op = o;
        ip += ip_step;
        op += op_step;
    }
}

// Fallback scalar kernel for any tail rows (total_rows % 4 != 0)
__global__ void __launch_bounds__(TPB)
hexa_tail_kernel(const float* __restrict__ hexa,
                 float* __restrict__ out,
                 int row_start, int total_rows) {
    int j = blockIdx.x * TPB + threadIdx.x;
    if (j >= CELLS) return;
    int src = src_index(j);
    for (int row = row_start + blockIdx.y; row < total_rows; row += gridDim.y) {
        float v = (src >= 0) ? __ldg(hexa + (size_t)row * IN_STRIDE + src) : 0.0f;
        out[(size_t)row * CELLS + j] = v;
    }
}

extern "C" void kernel_launch(void* const* d_in, const int* in_sizes, int n_in,
                              void* d_out, int out_size) {
    const float* hexa = (const float*)d_in[0];
    float* out = (float*)d_out;

    int total_rows = out_size / CELLS;       // 32768
    int n_super = total_rows / 4;            // 8192
    if (n_super > 0) {
        int threads = SLOTS * GROUPS;            // 605,098
        int blocks = (threads + TPB - 1) / TPB;  // 2364 (= 2 waves)
        hexa_direct_kernel<<<blocks, TPB>>>(hexa, out, n_super);
    }
    int done = n_super * 4;
    if (done < total_rows) {
        dim3 grid((CELLS + TPB - 1) / TPB, total_rows - done);
        hexa_tail_kernel<<<grid, TPB>>>(hexa, out, done, total_rows);
    }
}